// round 12
// baseline (speedup 1.0000x reference)
#include <cuda_runtime.h>
#include <cuda_bf16.h>
#include <cstdint>
#include <math.h>

#define BB 64
#define TT 512
#define NKV 512
#define DD 256
#define MTOT (BB*TT)
#define EPSLN 1e-5f

// ======================= scratch (device globals) ===========================
__device__ __align__(256) __nv_bfloat16 g_xh2[2*MTOT*DD];   // [0]=x, [1]=h
__device__ __align__(256) __nv_bfloat16 g_wqb[DD*DD];       // wq rows /16, bf16
__device__ __align__(256) __nv_bfloat16 g_wkb[DD*DD];       // wk rows, bf16
__device__ __align__(256) __nv_bfloat16 g_wvt[DD*DD];       // wv^T
__device__ __align__(256) __nv_bfloat16 g_G[DD*DD];         // G[j][d] = sum_e wk[j,e]wq[d,e]/16
__device__ __align__(256) __nv_bfloat16 g_A[MTOT*DD];       // A = x @ G^T-contract
__device__ __align__(256) __nv_bfloat16 g_vt[BB*DD*NKV];
__device__ __align__(256) float         g_cbv[DD];          // v = (Wk bq)/16
__device__ __align__(256) float         g_cb[MTOT];         // cb[b*NKV+n] = h_n . v
__device__ __align__(256) float         g_zero[DD];         // stays 0 (zero-init)
__device__ __align__(256) unsigned      g_poolu[BB*DD];

// ======================= PTX helpers (baseline ISA only) ====================
__device__ __forceinline__ uint32_t smem_to_u32(const void* p) {
    uint32_t a;
    asm("{ .reg .u64 t; cvta.to.shared.u64 t, %1; cvt.u32.u64 %0, t; }" : "=r"(a) : "l"(p));
    return a;
}
#define CP_ASYNC16(dst_u32, src_ptr) \
    asm volatile("cp.async.cg.shared.global [%0], [%1], 16;" \
        :: "r"(dst_u32), "l"(src_ptr))
#define CP_ASYNC_COMMIT() asm volatile("cp.async.commit_group;" ::: "memory")
#define CP_ASYNC_WAIT0()  asm volatile("cp.async.wait_group 0;" ::: "memory")
#define CP_ASYNC_WAIT1()  asm volatile("cp.async.wait_group 1;" ::: "memory")
#define CP_ASYNC_WAIT2()  asm volatile("cp.async.wait_group 2;" ::: "memory")
#define CP_ASYNC_WAIT3()  asm volatile("cp.async.wait_group 3;" ::: "memory")

__device__ __forceinline__ void ldsm4(uint32_t* r, uint32_t addr) {
    asm volatile("ldmatrix.sync.aligned.m8n8.x4.shared.b16 {%0,%1,%2,%3}, [%4];"
        : "=r"(r[0]), "=r"(r[1]), "=r"(r[2]), "=r"(r[3]) : "r"(addr));
}
__device__ __forceinline__ void mma_bf16(float* c, const uint32_t* a, const uint32_t* b) {
    asm volatile(
        "mma.sync.aligned.m16n8k16.row.col.f32.bf16.bf16.f32 "
        "{%0,%1,%2,%3}, {%4,%5,%6,%7}, {%8,%9}, {%0,%1,%2,%3};"
        : "+f"(c[0]), "+f"(c[1]), "+f"(c[2]), "+f"(c[3])
        : "r"(a[0]), "r"(a[1]), "r"(a[2]), "r"(a[3]), "r"(b[0]), "r"(b[1]));
}
__device__ __forceinline__ float lds_f32(uint32_t a) {
    float v; asm volatile("ld.shared.f32 %0, [%1];" : "=f"(v) : "r"(a)); return v;
}

// order-preserving float<->unsigned for atomicMax
__device__ __forceinline__ unsigned encf(float f) {
    unsigned u = __float_as_uint(f);
    return (u & 0x80000000u) ? ~u : (u | 0x80000000u);
}
__device__ __forceinline__ float decf(unsigned u) {
    unsigned b = (u & 0x80000000u) ? (u ^ 0x80000000u) : ~u;
    return __uint_as_float(b);
}
__device__ __forceinline__ uint32_t pack_bf16(float a, float b) {
    return (uint32_t)__bfloat16_as_ushort(__float2bfloat16(a))
         | ((uint32_t)__bfloat16_as_ushort(__float2bfloat16(b)) << 16);
}

// ======================= reductions =========================================
__device__ __forceinline__ float warp_sum(float v) {
    #pragma unroll
    for (int o = 16; o > 0; o >>= 1) v += __shfl_xor_sync(0xffffffffu, v, o);
    return v;
}
__device__ __forceinline__ float block_sum(float v, float* red) {
    int lane = threadIdx.x & 31, wid = threadIdx.x >> 5;
    v = warp_sum(v);
    if (lane == 0) red[wid] = v;
    __syncthreads();
    v = (threadIdx.x < (blockDim.x >> 5)) ? red[threadIdx.x] : 0.f;
    if (wid == 0) v = warp_sum(v);
    if (threadIdx.x == 0) red[0] = v;
    __syncthreads();
    v = red[0];
    __syncthreads();
    return v;
}

// ======================= elementwise kernels ================================
__global__ __launch_bounds__(256) void build_x_kernel(
    const float* __restrict__ traj, const int* __restrict__ labels,
    const float* __restrict__ w_mlp, const float* __restrict__ b_mlp,
    const float* __restrict__ ln_g, const float* __restrict__ ln_b,
    const float* __restrict__ emb)
{
    int wid  = threadIdx.x >> 5, lane = threadIdx.x & 31;
    int row  = blockIdx.x*8 + wid;
    int b    = row >> 9;
    int d0   = lane*8;
    float t0 = traj[row*2 + 0];
    float t1 = traj[row*2 + 1];

    float v[8];
    float lsum = 0.f;
    #pragma unroll
    for (int j = 0; j < 8; j += 4) {
        float4 wa = *(const float4*)&w_mlp[d0 + j];
        float4 wb = *(const float4*)&w_mlp[DD + d0 + j];
        float4 bm = *(const float4*)&b_mlp[d0 + j];
        v[j+0] = t0*wa.x + t1*wb.x + bm.x;
        v[j+1] = t0*wa.y + t1*wb.y + bm.y;
        v[j+2] = t0*wa.z + t1*wb.z + bm.z;
        v[j+3] = t0*wa.w + t1*wb.w + bm.w;
        lsum += v[j+0] + v[j+1] + v[j+2] + v[j+3];
    }
    float mean = warp_sum(lsum) * (1.f/DD);
    float lvar = 0.f;
    #pragma unroll
    for (int j = 0; j < 8; j++) { float dv = v[j] - mean; lvar += dv*dv; }
    float rstd = rsqrtf(warp_sum(lvar) * (1.f/DD) + EPSLN);

    int lab = labels[b];
    uint32_t ww[4];
    #pragma unroll
    for (int j = 0; j < 8; j += 2) {
        float y0 = (v[j]   - mean) * rstd * ln_g[d0+j]   + ln_b[d0+j];
        float y1 = (v[j+1] - mean) * rstd * ln_g[d0+j+1] + ln_b[d0+j+1];
        y0 = (y0 > 0.f) ? y0 : 0.01f*y0;
        y1 = (y1 > 0.f) ? y1 : 0.01f*y1;
        y0 += emb[lab*DD + d0 + j];
        y1 += emb[lab*DD + d0 + j + 1];
        ww[j>>1] = pack_bf16(y0, y1);
    }
    *(uint4*)&g_xh2[(long)row*DD + d0] = *(uint4*)ww;
}

// h -> bf16 into g_xh2 slot 1; also zero-init pool buffer
__global__ __launch_bounds__(256) void conv_bf16_kernel(
    const float* __restrict__ in, int n4)
{
    int i = blockIdx.x*256 + threadIdx.x;
    if (i < BB*DD) g_poolu[i] = 0u;
    if (i >= n4) return;
    float4 v = ((const float4*)in)[i];
    ((uint2*)(g_xh2 + (long)MTOT*DD))[i] =
        make_uint2(pack_bf16(v.x, v.y), pack_bf16(v.z, v.w));
}

// w=0: wv^T; w=1: wq rows /16 -> g_wqb; w=2: wk rows -> g_wkb + v=(Wk bq)/16
__global__ __launch_bounds__(256) void conv_w_kernel(
    const float* __restrict__ wq, const float* __restrict__ wk,
    const float* __restrict__ wv, const float* __restrict__ bq)
{
    __shared__ float red[32];
    int w = blockIdx.x >> 8;
    int r = blockIdx.x & 255;
    int c = threadIdx.x;
    if (w == 0) {
        g_wvt[r*DD + c] = __float2bfloat16(wv[c*DD + r]);
    } else if (w == 1) {
        g_wqb[r*DD + c] = __float2bfloat16(wq[r*DD + c] * 0.0625f);
    } else {
        float val = wk[r*DD + c];
        g_wkb[r*DD + c] = __float2bfloat16(val);
        float s = block_sum(val * bq[c], red);
        if (c == 0) g_cbv[r] = s * 0.0625f;
    }
}

// cb[row] = h_row . v   (warp per row over 32768 rows)
__global__ __launch_bounds__(256) void cb_kernel()
{
    int wid = threadIdx.x >> 5, lane = threadIdx.x & 31;
    int row = blockIdx.x*8 + wid;
    int d0  = lane*8;
    const __nv_bfloat16* hr = g_xh2 + (long)MTOT*DD + (long)row*DD + d0;
    uint4 hw = *(const uint4*)hr;
    float4 v0 = *(const float4*)&g_cbv[d0];
    float4 v1 = *(const float4*)&g_cbv[d0 + 4];
    uint32_t u[4] = {hw.x, hw.y, hw.z, hw.w};
    float hv[8];
    #pragma unroll
    for (int j = 0; j < 4; j++) {
        hv[2*j]   = __bfloat162float(__ushort_as_bfloat16((unsigned short)(u[j] & 0xffffu)));
        hv[2*j+1] = __bfloat162float(__ushort_as_bfloat16((unsigned short)(u[j] >> 16)));
    }
    float s = hv[0]*v0.x + hv[1]*v0.y + hv[2]*v0.z + hv[3]*v0.w
            + hv[4]*v1.x + hv[5]*v1.y + hv[6]*v1.z + hv[7]*v1.w;
    s = warp_sum(s);
    if (lane == 0) g_cb[row] = s;
}

__global__ __launch_bounds__(256) void pool_out_kernel(
    const int* __restrict__ labels, const float* __restrict__ emb,
    const float* __restrict__ w_out, const float* __restrict__ b_out,
    float* __restrict__ out)
{
    __shared__ float red[32];
    int b = blockIdx.x;
    int d = threadIdx.x;
    float m = decf(g_poolu[b*DD + d]);
    float p = m + emb[labels[b]*DD + d];
    float sum = block_sum(p * w_out[d], red);
    if (threadIdx.x == 0)
        out[b] = 1.f / (1.f + __expf(-(sum + b_out[0])));
}

// ======================= mma.sync GEMM ======================================
// C[m,n] = sum_k A[m,k]*B[n,k] (+ bias). MODE 1: +bias[n]. MODE 2: +bias[m].
// VLM 0: none. VLM 2: exit if n0 >= vl[z].
#define LDSROW   80
#define A_SB     (128*LDSROW)
#define B_SB     (128*LDSROW)
#define STAGE    (A_SB + B_SB)
#define NSTAGE   4
#define SMEM_REQ (NSTAGE*STAGE)      // 81920 B

template<int MODE, int VLM>
__global__ __launch_bounds__(256, 2) void mma_gemm_kernel(
    const __nv_bfloat16* __restrict__ A, const __nv_bfloat16* __restrict__ B,
    const float* __restrict__ bias, __nv_bfloat16* __restrict__ Cb,
    const int* __restrict__ vlen,
    int N, int K, long sA, long sB, long sC)
{
    extern __shared__ char dsm[];
    const uint32_t sm0 = smem_to_u32(dsm);

    const int tid  = threadIdx.x;
    const int lane = tid & 31;
    const int w    = tid >> 5;
    const int wm   = w & 3;
    const int wn   = w >> 2;

    const int m0 = blockIdx.y * 128;
    const int n0 = blockIdx.x * 128;

    int nch = K >> 5;
    if (VLM == 2) { if (n0 >= vlen[blockIdx.z]) return; }

    A += (long)blockIdx.z * sA;
    B += (long)blockIdx.z * sB;
    const long czoff = (long)blockIdx.z * sC;

    float acc[2][8][4] = {};

    auto prefetch = [&](int c) {
        const int kc = c << 5;
        const uint32_t sb = sm0 + (c & (NSTAGE-1)) * STAGE;
        #pragma unroll
        for (int t = 0; t < 4; t++) {
            int idx = t*256 + tid;
            int row = (idx >> 2) & 127, seg = idx & 3;
            if (idx < 512) {
                CP_ASYNC16(sb + row*LDSROW + seg*16,
                           A + (long)(m0 + row)*K + kc + seg*8);
            } else {
                CP_ASYNC16(sb + A_SB + row*LDSROW + seg*16,
                           B + (long)(n0 + row)*K + kc + seg*8);
            }
        }
        CP_ASYNC_COMMIT();
    };

    for (int p = 0; p < 3 && p < nch; p++) prefetch(p);

    for (int c = 0; c < nch; c++) {
        if (c + 3 < nch)      { prefetch(c + 3); CP_ASYNC_WAIT3(); }
        else if (c + 2 < nch) { CP_ASYNC_WAIT2(); }
        else if (c + 1 < nch) { CP_ASYNC_WAIT1(); }
        else                  { CP_ASYNC_WAIT0(); }
        __syncthreads();

        const uint32_t sb = sm0 + (c & (NSTAGE-1)) * STAGE;
        #pragma unroll
        for (int ks = 0; ks < 2; ks++) {
            uint32_t aF[2][4], bF[8][2];
            {
                const int arow = wm*32 + (lane & 15);
                const int acol = (ks*16 + ((lane >> 4) & 1)*8) * 2;
                #pragma unroll
                for (int mt = 0; mt < 2; mt++)
                    ldsm4(aF[mt], sb + (arow + mt*16)*LDSROW + acol);
            }
            {
                const int bcol = (ks*16 + ((lane >> 3) & 1)*8) * 2;
                #pragma unroll
                for (int g = 0; g < 4; g++) {
                    const int brow = wn*64 + g*16 + ((lane >> 4) & 1)*8 + (lane & 7);
                    uint32_t t4[4];
                    ldsm4(t4, sb + A_SB + brow*LDSROW + bcol);
                    bF[2*g+0][0] = t4[0]; bF[2*g+0][1] = t4[1];
                    bF[2*g+1][0] = t4[2]; bF[2*g+1][1] = t4[3];
                }
            }
            #pragma unroll
            for (int mt = 0; mt < 2; mt++)
                #pragma unroll
                for (int nt = 0; nt < 8; nt++)
                    mma_bf16(acc[mt][nt], aF[mt], bF[nt]);
        }
        __syncthreads();
    }

    #pragma unroll
    for (int mt = 0; mt < 2; mt++) {
        #pragma unroll
        for (int nt = 0; nt < 8; nt++) {
            int mg = m0 + wm*32 + mt*16 + (lane >> 2);
            int ng = n0 + wn*64 + nt*8 + (lane & 3)*2;
            float v0 = acc[mt][nt][0], v1 = acc[mt][nt][1];
            float v2 = acc[mt][nt][2], v3 = acc[mt][nt][3];
            if (MODE == 1) {
                float b0 = bias[ng], b1 = bias[ng+1];
                v0 += b0; v1 += b1; v2 += b0; v3 += b1;
            } else {
                float b0 = bias[mg], b1 = bias[mg+8];
                v0 += b0; v1 += b0; v2 += b1; v3 += b1;
            }
            *(uint32_t*)&Cb[czoff + (long)mg*N + ng]     = pack_bf16(v0, v1);
            *(uint32_t*)&Cb[czoff + (long)(mg+8)*N + ng] = pack_bf16(v2, v3);
        }
    }
}

// ======================= flash attention ====================================
// CTA: 64 q-rows of one batch, 8 warps = 4 q-groups x 2 d-halves.
// S = A@h^T + cb (computed per q-group, duplicated across d-halves);
// online softmax warp-local; O (16x128 per warp) in 64 regs -> no spills.
#define QROW   528
#define KROW   528
#define VROW   144
#define Q_SB   (64*QROW)             // 33792
#define K_SB   (64*KROW)             // 33792
#define V_SB   (256*VROW)            // 36864
#define CB_SB  256
#define KV_SB  (K_SB + V_SB + CB_SB) // 70912
#define FL_SMEM (Q_SB + 2*KV_SB)     // 175616

__global__ __launch_bounds__(256, 1) void flash_kernel(const int* __restrict__ vlen)
{
    extern __shared__ char dsm[];
    const uint32_t smQ  = smem_to_u32(dsm);
    const uint32_t smKV = smQ + Q_SB;
    const int tid = threadIdx.x, lane = tid & 31, wid = tid >> 5;
    const int g  = wid & 3;          // q-group (16 rows)
    const int hf = wid >> 2;         // d-half (128 cols)
    const int b = blockIdx.y, qt = blockIdx.x;
    const int vl = vlen[b];
    const int ntiles = (vl + 63) >> 6;

    const __nv_bfloat16* Qg = g_A + ((long)(b*TT + qt*64))*DD;
    const __nv_bfloat16* Kg = g_xh2 + (long)MTOT*DD + (long)b*NKV*DD;   // h
    const __nv_bfloat16* Vg = g_vt + (long)b*DD*NKV;
    const float*         Cg = g_cb + b*NKV;

    // Q tile: 64 rows x 32 16B-segs = 2048 copies
    #pragma unroll
    for (int t = 0; t < 8; t++) {
        int idx = t*256 + tid, row = idx >> 5, seg = idx & 31;
        CP_ASYNC16(smQ + row*QROW + seg*16, Qg + (long)row*DD + seg*8);
    }
    CP_ASYNC_COMMIT();

    auto prefetchKV = [&](int kt) {
        uint32_t sb = smKV + (kt & 1) * KV_SB;
        #pragma unroll
        for (int t = 0; t < 16; t++) {
            int idx = t*256 + tid;
            if (idx < 2048) {                 // K(h): 64 key-rows x 32 segs
                int row = idx >> 5, seg = idx & 31;
                CP_ASYNC16(sb + row*KROW + seg*16,
                           Kg + (long)(kt*64 + row)*DD + seg*8);
            } else {                          // V^T: 256 d-rows x 8 segs
                int j = idx - 2048;
                int row = j >> 3, seg = j & 7;
                CP_ASYNC16(sb + K_SB + row*VROW + seg*16,
                           Vg + (long)row*NKV + kt*64 + seg*8);
            }
        }
        if (tid < 16)                         // cb: 64 floats = 16 segs
            CP_ASYNC16(sb + K_SB + V_SB + tid*16, Cg + kt*64 + tid*4);
        CP_ASYNC_COMMIT();
    };
    prefetchKV(0);

    float o[16][4];
    #pragma unroll
    for (int i = 0; i < 16; i++) o[i][0] = o[i][1] = o[i][2] = o[i][3] = 0.f;
    float m0 = -1e30f, m1 = -1e30f, l0 = 0.f, l1 = 0.f;

    for (int kt = 0; kt < ntiles; kt++) {
        if (kt + 1 < ntiles) {
            __syncthreads();
            prefetchKV(kt + 1);
            CP_ASYNC_WAIT1();
        } else {
            CP_ASYNC_WAIT0();
        }
        __syncthreads();
        const uint32_t sb = smKV + (kt & 1) * KV_SB;

        // ---- S = A_tile @ h_tile^T + cb  (16 q x 64 keys) ----
        float s[8][4] = {};
        #pragma unroll
        for (int ks = 0; ks < 16; ks++) {
            uint32_t aF[4];
            ldsm4(aF, smQ + (g*16 + (lane & 15))*QROW
                        + (ks*16 + ((lane >> 4) & 1)*8)*2);
            #pragma unroll
            for (int g2 = 0; g2 < 4; g2++) {
                uint32_t t4[4];
                ldsm4(t4, sb + (g2*16 + ((lane >> 4) & 1)*8 + (lane & 7))*KROW
                            + (ks*16 + ((lane >> 3) & 1)*8)*2);
                mma_bf16(s[2*g2+0], aF, t4);
                mma_bf16(s[2*g2+1], aF, t4 + 2);
            }
        }
        // ---- + col bias cb, mask tail ----
        {
            uint32_t cbb = sb + K_SB + V_SB;
            #pragma unroll
            for (int nt = 0; nt < 8; nt++) {
                int col = nt*8 + 2*(lane & 3);
                float c0 = lds_f32(cbb + col*4);
                float c1 = lds_f32(cbb + col*4 + 4);
                s[nt][0] += c0; s[nt][1] += c1;
                s[nt][2] += c0; s[nt][3] += c1;
            }
        }
        if (kt == ntiles - 1) {
            int kbase = kt*64 + 2*(lane & 3);
            #pragma unroll
            for (int nt = 0; nt < 8; nt++) {
                int k0 = kbase + nt*8;
                if (k0     >= vl) { s[nt][0] = -1e9f; s[nt][2] = -1e9f; }
                if (k0 + 1 >= vl) { s[nt][1] = -1e9f; s[nt][3] = -1e9f; }
            }
        }
        // ---- online softmax (rows lane>>2 and +8) ----
        float rm0 = -1e30f, rm1 = -1e30f;
        #pragma unroll
        for (int nt = 0; nt < 8; nt++) {
            rm0 = fmaxf(rm0, fmaxf(s[nt][0], s[nt][1]));
            rm1 = fmaxf(rm1, fmaxf(s[nt][2], s[nt][3]));
        }
        rm0 = fmaxf(rm0, __shfl_xor_sync(0xffffffffu, rm0, 1));
        rm0 = fmaxf(rm0, __shfl_xor_sync(0xffffffffu, rm0, 2));
        rm1 = fmaxf(rm1, __shfl_xor_sync(0xffffffffu, rm1, 1));
        rm1 = fmaxf(rm1, __shfl_xor_sync(0xffffffffu, rm1, 2));
        float m0n = fmaxf(m0, rm0), m1n = fmaxf(m1, rm1);
        float f0 = __expf(m0 - m0n), f1 = __expf(m1 - m1n);

        float ts0 = 0.f, ts1 = 0.f;
        #pragma unroll
        for (int nt = 0; nt < 8; nt++) {
            s[nt][0] = __expf(s[nt][0] - m0n);
            s[nt][1] = __expf(s[nt][1] - m0n);
            s[nt][2] = __expf(s[nt][2] - m1n);
            s[nt][3] = __expf(s[nt][3] - m1n);
            ts0 += s[nt][0] + s[nt][1];
            ts1 += s[nt][2] + s[nt][3];
        }
        ts0 += __shfl_xor_sync(0xffffffffu, ts0, 1);
        ts0 += __shfl_xor_sync(0xffffffffu, ts0, 2);
        ts1 += __shfl_xor_sync(0xffffffffu, ts1, 1);
        ts1 += __shfl_xor_sync(0xffffffffu, ts1, 2);
        l0 = l0*f0 + ts0;  l1 = l1*f1 + ts1;
        m0 = m0n;          m1 = m1n;
        #pragma unroll
        for (int dt = 0; dt < 16; dt++) {
            o[dt][0] *= f0; o[dt][1] *= f0;
            o[dt][2] *= f1; o[dt][3] *= f1;
        }
        // ---- O += P @ V on this warp's d-half ----
        #pragma unroll
        for (int j = 0; j < 4; j++) {
            uint32_t pa[4] = {
                pack_bf16(s[2*j][0],   s[2*j][1]),
                pack_bf16(s[2*j][2],   s[2*j][3]),
                pack_bf16(s[2*j+1][0], s[2*j+1][1]),
                pack_bf16(s[2*j+1][2], s[2*j+1][3])
            };
            #pragma unroll
            for (int dt2 = 0; dt2 < 8; dt2++) {
                uint32_t t4[4];
                ldsm4(t4, sb + K_SB
                          + ((hf*8 + dt2)*16 + ((lane >> 4) & 1)*8 + (lane & 7))*VROW
                          + (j*16 + ((lane >> 3) & 1)*8)*2);
                mma_bf16(o[2*dt2+0], pa, t4);
                mma_bf16(o[2*dt2+1], pa, t4 + 2);
            }
        }
    }

    // ---- epilogue: normalize, pooled max over q-rows, atomicMax ----
    float inv0 = 1.f / l0, inv1 = 1.f / l1;
    #pragma unroll
    for (int dtl = 0; dtl < 16; dtl++) {
        float c0 = fmaxf(o[dtl][0]*inv0, o[dtl][2]*inv1);
        float c1 = fmaxf(o[dtl][1]*inv0, o[dtl][3]*inv1);
        #pragma unroll
        for (int off = 4; off < 32; off <<= 1) {
            c0 = fmaxf(c0, __shfl_xor_sync(0xffffffffu, c0, off));
            c1 = fmaxf(c1, __shfl_xor_sync(0xffffffffu, c1, off));
        }
        if (lane < 4) {
            int d = (hf*16 + dtl)*8 + 2*lane;
            atomicMax(&g_poolu[b*DD + d],     encf(c0));
            atomicMax(&g_poolu[b*DD + d + 1], encf(c1));
        }
    }
}

// ======================= launch =============================================
extern "C" void kernel_launch(void* const* d_in, const int* in_sizes, int n_in,
                              void* d_out, int out_size)
{
    const float* traj      = (const float*)d_in[0];
    const int*   labels    = (const int*)  d_in[1];
    const float* h         = (const float*)d_in[2];
    const int*   valid_len = (const int*)  d_in[3];
    const float* emb       = (const float*)d_in[4];
    const float* w_mlp     = (const float*)d_in[5];
    const float* b_mlp     = (const float*)d_in[6];
    const float* ln_g      = (const float*)d_in[7];
    const float* ln_b      = (const float*)d_in[8];
    const float* wq        = (const float*)d_in[9];
    const float* wk        = (const float*)d_in[11];
    const float* wv        = (const float*)d_in[13];
    const float* bq        = (const float*)d_in[10];
    const float* bv        = (const float*)d_in[14];
    const float* w_out     = (const float*)d_in[15];
    const float* b_out     = (const float*)d_in[16];
    float* out = (float*)d_out;

    cudaFuncSetAttribute(mma_gemm_kernel<1,0>, cudaFuncAttributeMaxDynamicSharedMemorySize, SMEM_REQ);
    cudaFuncSetAttribute(mma_gemm_kernel<2,2>, cudaFuncAttributeMaxDynamicSharedMemorySize, SMEM_REQ);
    cudaFuncSetAttribute(flash_kernel, cudaFuncAttributeMaxDynamicSharedMemorySize, FL_SMEM);

    __nv_bfloat16 *pxh2, *pwqb, *pwkb, *pwvt, *pG, *pA, *pvt;
    float *pzero;
    cudaGetSymbolAddress((void**)&pxh2,  g_xh2);
    cudaGetSymbolAddress((void**)&pwqb,  g_wqb);
    cudaGetSymbolAddress((void**)&pwkb,  g_wkb);
    cudaGetSymbolAddress((void**)&pwvt,  g_wvt);
    cudaGetSymbolAddress((void**)&pG,    g_G);
    cudaGetSymbolAddress((void**)&pA,    g_A);
    cudaGetSymbolAddress((void**)&pvt,   g_vt);
    cudaGetSymbolAddress((void**)&pzero, g_zero);

    // 1. x = leaky(LN(traj@w_mlp)) + le -> bf16 (slot 0)
    build_x_kernel<<<MTOT/8, 256>>>(traj, labels, w_mlp, b_mlp, ln_g, ln_b, emb);
    // 2. h -> bf16 (slot 1) + pool init
    conv_bf16_kernel<<<(MTOT*DD/4 + 255)/256, 256>>>(h, MTOT*DD/4);
    // 3. weight converts: wv^T, wq/16 rows, wk rows + v=(Wk bq)/16
    conv_w_kernel<<<3*DD, DD>>>(wq, wk, wv, bq);
    // 4. G[j,d] = sum_e wkb[j,e]*wqb[d,e]   (tiny 256x256x256)
    mma_gemm_kernel<1,0><<<dim3(2, 2, 1), 256, SMEM_REQ>>>(
        pwkb, pwqb, pzero, pG, valid_len, DD, DD, 0, 0, 0);
    // 5. cb[row] = h_row . v
    cb_kernel<<<MTOT/8, 256>>>();
    // 6. A = x @ G^T-contract   (replaces q AND k projections)
    mma_gemm_kernel<1,0><<<dim3(2, 256, 1), 256, SMEM_REQ>>>(
        pxh2, pG, pzero, pA, valid_len, DD, DD, 0, 0, 0);
    // 7. vT[b][d][n] = wvT @ h^T + bv[d]  (skip n-tiles >= vl)
    mma_gemm_kernel<2,2><<<dim3(4, 2, BB), 256, SMEM_REQ>>>(
        pwvt, pxh2 + (long)MTOT*DD, bv, pvt, valid_len,
        NKV, DD, 0, (long)NKV*DD, (long)DD*NKV);
    // 8. flash: S=A@h^T+cb, softmax, PV, max-pool (fused)
    flash_kernel<<<dim3(8, BB), 256, FL_SMEM>>>(valid_len);
    // 9. output = sigmoid((pooled + le) @ w_out + b_out)
    pool_out_kernel<<<BB, 256>>>(labels, emb, w_out, b_out, out);
}

// round 13
// speedup vs baseline: 1.0759x; 1.0759x over previous
#include <cuda_runtime.h>
#include <cuda_bf16.h>
#include <cstdint>
#include <math.h>

#define BB 64
#define TT 512
#define NKV 512
#define DD 256
#define MTOT (BB*TT)
#define EPSLN 1e-5f

// ======================= scratch (device globals) ===========================
__device__ __align__(256) __nv_bfloat16 g_xh2[2*MTOT*DD];   // [0]=x, [1]=h
__device__ __align__(256) __nv_bfloat16 g_wt2[2*DD*DD];     // [0]=wqT(/16), [1]=wkT
__device__ __align__(256) __nv_bfloat16 g_wvt[DD*DD];
__device__ __align__(256) float         g_b2[2*DD];         // bq/16, bk
__device__ __align__(256) __nv_bfloat16 g_qk[2*MTOT*DD];    // [0]=q/16, [1]=k
__device__ __align__(256) __nv_bfloat16 g_vt[BB*DD*NKV];
__device__ __align__(256) unsigned      g_poolu[BB*DD];

// ======================= PTX helpers (baseline ISA only) ====================
__device__ __forceinline__ uint32_t smem_to_u32(const void* p) {
    uint32_t a;
    asm("{ .reg .u64 t; cvta.to.shared.u64 t, %1; cvt.u32.u64 %0, t; }" : "=r"(a) : "l"(p));
    return a;
}
#define CP_ASYNC16(dst_u32, src_ptr) \
    asm volatile("cp.async.cg.shared.global [%0], [%1], 16;" \
        :: "r"(dst_u32), "l"(src_ptr))
#define CP_ASYNC_COMMIT() asm volatile("cp.async.commit_group;" ::: "memory")
#define CP_ASYNC_WAIT0()  asm volatile("cp.async.wait_group 0;" ::: "memory")
#define CP_ASYNC_WAIT1()  asm volatile("cp.async.wait_group 1;" ::: "memory")
#define CP_ASYNC_WAIT2()  asm volatile("cp.async.wait_group 2;" ::: "memory")

__device__ __forceinline__ void ldsm4(uint32_t* r, uint32_t addr) {
    asm volatile("ldmatrix.sync.aligned.m8n8.x4.shared.b16 {%0,%1,%2,%3}, [%4];"
        : "=r"(r[0]), "=r"(r[1]), "=r"(r[2]), "=r"(r[3]) : "r"(addr));
}
__device__ __forceinline__ void mma_bf16(float* c, const uint32_t* a, const uint32_t* b) {
    asm volatile(
        "mma.sync.aligned.m16n8k16.row.col.f32.bf16.bf16.f32 "
        "{%0,%1,%2,%3}, {%4,%5,%6,%7}, {%8,%9}, {%0,%1,%2,%3};"
        : "+f"(c[0]), "+f"(c[1]), "+f"(c[2]), "+f"(c[3])
        : "r"(a[0]), "r"(a[1]), "r"(a[2]), "r"(a[3]), "r"(b[0]), "r"(b[1]));
}

// order-preserving float<->unsigned for atomicMax
__device__ __forceinline__ unsigned encf(float f) {
    unsigned u = __float_as_uint(f);
    return (u & 0x80000000u) ? ~u : (u | 0x80000000u);
}
__device__ __forceinline__ float decf(unsigned u) {
    unsigned b = (u & 0x80000000u) ? (u ^ 0x80000000u) : ~u;
    return __uint_as_float(b);
}
__device__ __forceinline__ uint32_t pack_bf16(float a, float b) {
    return (uint32_t)__bfloat16_as_ushort(__float2bfloat16(a))
         | ((uint32_t)__bfloat16_as_ushort(__float2bfloat16(b)) << 16);
}

// ======================= reductions =========================================
__device__ __forceinline__ float warp_sum(float v) {
    #pragma unroll
    for (int o = 16; o > 0; o >>= 1) v += __shfl_xor_sync(0xffffffffu, v, o);
    return v;
}
__device__ __forceinline__ float block_sum(float v, float* red) {
    int lane = threadIdx.x & 31, wid = threadIdx.x >> 5;
    v = warp_sum(v);
    if (lane == 0) red[wid] = v;
    __syncthreads();
    v = (threadIdx.x < (blockDim.x >> 5)) ? red[threadIdx.x] : 0.f;
    if (wid == 0) v = warp_sum(v);
    if (threadIdx.x == 0) red[0] = v;
    __syncthreads();
    v = red[0];
    __syncthreads();
    return v;
}

// ======================= elementwise kernels ================================
__global__ __launch_bounds__(256) void build_x_kernel(
    const float* __restrict__ traj, const int* __restrict__ labels,
    const float* __restrict__ w_mlp, const float* __restrict__ b_mlp,
    const float* __restrict__ ln_g, const float* __restrict__ ln_b,
    const float* __restrict__ emb)
{
    int wid  = threadIdx.x >> 5, lane = threadIdx.x & 31;
    int row  = blockIdx.x*8 + wid;
    int b    = row >> 9;
    int d0   = lane*8;
    float t0 = traj[row*2 + 0];
    float t1 = traj[row*2 + 1];

    float v[8];
    float lsum = 0.f;
    #pragma unroll
    for (int j = 0; j < 8; j += 4) {
        float4 wa = *(const float4*)&w_mlp[d0 + j];
        float4 wb = *(const float4*)&w_mlp[DD + d0 + j];
        float4 bm = *(const float4*)&b_mlp[d0 + j];
        v[j+0] = t0*wa.x + t1*wb.x + bm.x;
        v[j+1] = t0*wa.y + t1*wb.y + bm.y;
        v[j+2] = t0*wa.z + t1*wb.z + bm.z;
        v[j+3] = t0*wa.w + t1*wb.w + bm.w;
        lsum += v[j+0] + v[j+1] + v[j+2] + v[j+3];
    }
    float mean = warp_sum(lsum) * (1.f/DD);
    float lvar = 0.f;
    #pragma unroll
    for (int j = 0; j < 8; j++) { float dv = v[j] - mean; lvar += dv*dv; }
    float rstd = rsqrtf(warp_sum(lvar) * (1.f/DD) + EPSLN);

    int lab = labels[b];
    uint32_t ww[4];
    #pragma unroll
    for (int j = 0; j < 8; j += 2) {
        float y0 = (v[j]   - mean) * rstd * ln_g[d0+j]   + ln_b[d0+j];
        float y1 = (v[j+1] - mean) * rstd * ln_g[d0+j+1] + ln_b[d0+j+1];
        y0 = (y0 > 0.f) ? y0 : 0.01f*y0;
        y1 = (y1 > 0.f) ? y1 : 0.01f*y1;
        y0 += emb[lab*DD + d0 + j];
        y1 += emb[lab*DD + d0 + j + 1];
        ww[j>>1] = pack_bf16(y0, y1);
    }
    *(uint4*)&g_xh2[(long)row*DD + d0] = *(uint4*)ww;
}

// h -> bf16 into g_xh2 slot 1; also zero-init pool buffer
__global__ __launch_bounds__(256) void conv_bf16_kernel(
    const float* __restrict__ in, int n4)
{
    int i = blockIdx.x*256 + threadIdx.x;
    if (i < BB*DD) g_poolu[i] = 0u;
    if (i >= n4) return;
    float4 v = ((const float4*)in)[i];
    ((uint2*)(g_xh2 + (long)MTOT*DD))[i] =
        make_uint2(pack_bf16(v.x, v.y), pack_bf16(v.z, v.w));
}

// wq,wk,wv [k][n] -> transposed bf16; wq and bq pre-scaled by 1/16 (1/sqrt(D))
__global__ __launch_bounds__(256) void convT_all_kernel(
    const float* __restrict__ wq, const float* __restrict__ wk,
    const float* __restrict__ wv,
    const float* __restrict__ bq, const float* __restrict__ bk)
{
    int w = blockIdx.x >> 8;     // 0..2
    int n = blockIdx.x & 255;
    int k = threadIdx.x;
    const float* src = (w == 0) ? wq : (w == 1) ? wk : wv;
    __nv_bfloat16* dst = (w == 0) ? g_wt2 : (w == 1) ? (g_wt2 + DD*DD) : g_wvt;
    float sc = (w == 0) ? 0.0625f : 1.f;
    dst[n*DD + k] = __float2bfloat16(src[k*DD + n] * sc);
    if (blockIdx.x == 0) g_b2[k] = bq[k] * 0.0625f;
    if (blockIdx.x == 1) g_b2[DD + k] = bk[k];
}

__global__ __launch_bounds__(256) void pool_out_kernel(
    const int* __restrict__ labels, const float* __restrict__ emb,
    const float* __restrict__ w_out, const float* __restrict__ b_out,
    float* __restrict__ out)
{
    __shared__ float red[32];
    int b = blockIdx.x;
    int d = threadIdx.x;
    float m = decf(g_poolu[b*DD + d]);
    float p = m + emb[labels[b]*DD + d];
    float sum = block_sum(p * w_out[d], red);
    if (threadIdx.x == 0)
        out[b] = 1.f / (1.f + __expf(-(sum + b_out[0])));
}

// ======================= mma.sync GEMM (projections) ========================
// C[m,n] = sum_k A[m,k]*B[n,k] + bias.  MODE 1: bias[z*sBias+n]. MODE 2: bias[m].
// VLM 2: exit if n0 >= vl[z]. VLM 3: exit if z==1 && (m0&511) >= vl[m0>>9].
// Block tile 128x128, K-chunk 64, 3-stage cp.async pipeline, 8 warps (4m x 2n),
// warp tile 32x64. 2 CTAs/SM (regs<=128, smem 108KB/CTA).
#define LDSROW   144                 // 64 bf16 (128B) + 16B pad
#define A_SB     (128*LDSROW)        // 18432 B
#define B_SB     (128*LDSROW)        // 18432 B
#define STAGE    (A_SB + B_SB)       // 36864 B
#define NSTAGE   3
#define SMEM_REQ (NSTAGE*STAGE)      // 110592 B

template<int MODE, int VLM>
__global__ __launch_bounds__(256, 2) void mma_gemm_kernel(
    const __nv_bfloat16* __restrict__ A, const __nv_bfloat16* __restrict__ B,
    const float* __restrict__ bias, __nv_bfloat16* __restrict__ Cb,
    const int* __restrict__ vlen,
    int N, int K, long sA, long sB, long sC, long sBias)
{
    extern __shared__ char dsm[];
    const uint32_t sm0 = smem_to_u32(dsm);

    const int tid  = threadIdx.x;
    const int lane = tid & 31;
    const int w    = tid >> 5;
    const int wm   = w & 3;
    const int wn   = w >> 2;

    const int m0 = blockIdx.y * 128;
    const int n0 = blockIdx.x * 128;

    const int nch = K >> 6;
    if (VLM == 2) { if (n0 >= vlen[blockIdx.z]) return; }
    if (VLM == 3) { if (blockIdx.z == 1 && (m0 & 511) >= vlen[m0 >> 9]) return; }

    A += (long)blockIdx.z * sA;
    B += (long)blockIdx.z * sB;
    const long czoff = (long)blockIdx.z * sC;

    float acc[2][8][4] = {};

    // K-chunk 64 bf16 = 8 x 16B segs/row. A: 128x8=1024, B: 1024 -> 8 iters.
    auto prefetch = [&](int c) {
        const int kc = c << 6;
        const uint32_t sb = sm0 + (c % NSTAGE) * STAGE;
        #pragma unroll
        for (int t = 0; t < 8; t++) {
            int idx = t*256 + tid;
            int row = (idx >> 3) & 127, seg = idx & 7;
            if (idx < 1024) {
                CP_ASYNC16(sb + row*LDSROW + seg*16,
                           A + (long)(m0 + row)*K + kc + seg*8);
            } else {
                CP_ASYNC16(sb + A_SB + row*LDSROW + seg*16,
                           B + (long)(n0 + row)*K + kc + seg*8);
            }
        }
        CP_ASYNC_COMMIT();
    };

    prefetch(0);
    if (nch > 1) prefetch(1);

    for (int c = 0; c < nch; c++) {
        if (c + 2 < nch)      { prefetch(c + 2); CP_ASYNC_WAIT2(); }
        else if (c + 1 < nch) { CP_ASYNC_WAIT1(); }
        else                  { CP_ASYNC_WAIT0(); }
        __syncthreads();

        const uint32_t sb = sm0 + (c % NSTAGE) * STAGE;
        #pragma unroll
        for (int ks = 0; ks < 4; ks++) {
            uint32_t aF[2][4], bF[8][2];
            {
                const int arow = wm*32 + (lane & 15);
                const int acol = (ks*16 + ((lane >> 4) & 1)*8) * 2;
                #pragma unroll
                for (int mt = 0; mt < 2; mt++)
                    ldsm4(aF[mt], sb + (arow + mt*16)*LDSROW + acol);
            }
            {
                const int bcol = (ks*16 + ((lane >> 3) & 1)*8) * 2;
                #pragma unroll
                for (int g = 0; g < 4; g++) {
                    const int brow = wn*64 + g*16 + ((lane >> 4) & 1)*8 + (lane & 7);
                    uint32_t t4[4];
                    ldsm4(t4, sb + A_SB + brow*LDSROW + bcol);
                    bF[2*g+0][0] = t4[0]; bF[2*g+0][1] = t4[1];
                    bF[2*g+1][0] = t4[2]; bF[2*g+1][1] = t4[3];
                }
            }
            #pragma unroll
            for (int mt = 0; mt < 2; mt++)
                #pragma unroll
                for (int nt = 0; nt < 8; nt++)
                    mma_bf16(acc[mt][nt], aF[mt], bF[nt]);
        }
        __syncthreads();
    }

    #pragma unroll
    for (int mt = 0; mt < 2; mt++) {
        #pragma unroll
        for (int nt = 0; nt < 8; nt++) {
            int mg = m0 + wm*32 + mt*16 + (lane >> 2);
            int ng = n0 + wn*64 + nt*8 + (lane & 3)*2;
            float v0 = acc[mt][nt][0], v1 = acc[mt][nt][1];
            float v2 = acc[mt][nt][2], v3 = acc[mt][nt][3];
            if (MODE == 1) {
                float b0 = bias[blockIdx.z*sBias + ng], b1 = bias[blockIdx.z*sBias + ng + 1];
                v0 += b0; v1 += b1; v2 += b0; v3 += b1;
            } else {
                float b0 = bias[mg], b1 = bias[mg+8];
                v0 += b0; v1 += b0; v2 += b1; v3 += b1;
            }
            *(uint32_t*)&Cb[czoff + (long)mg*N + ng]     = pack_bf16(v0, v1);
            *(uint32_t*)&Cb[czoff + (long)(mg+8)*N + ng] = pack_bf16(v2, v3);
        }
    }
}

// ======================= flash attention (scores+softmax+PV+pool) ===========
// CTA: 128 q-rows of one batch. 8 warps, warp owns 16 q-rows x all keys.
// kv-tiles of 64 keys, double-buffered. O accumulated in regs; epilogue
// normalizes and atomicMax-pools. q is pre-scaled by 1/sqrt(D).
#define QROW   528                   // 256 bf16 (512B) + 16B pad
#define KROW   528
#define VROW   144                   // 64 bf16 (128B) + 16B pad
#define Q_SB   (128*QROW)            // 67584
#define K_SB   (64*KROW)             // 33792
#define V_SB   (256*VROW)            // 36864
#define KV_SB  (K_SB + V_SB)         // 70656
#define FL_SMEM (Q_SB + 2*KV_SB)     // 208896

__global__ __launch_bounds__(256, 1) void flash_kernel(const int* __restrict__ vlen)
{
    extern __shared__ char dsm[];
    const uint32_t smQ  = smem_to_u32(dsm);
    const uint32_t smKV = smQ + Q_SB;
    const int tid = threadIdx.x, lane = tid & 31, wid = tid >> 5;
    const int b = blockIdx.y, qt = blockIdx.x;
    const int vl = vlen[b];
    const int ntiles = (vl + 63) >> 6;

    const __nv_bfloat16* Qg = g_qk + ((long)(b*TT + qt*128))*DD;
    const __nv_bfloat16* Kg = g_qk + (long)MTOT*DD + (long)b*NKV*DD;
    const __nv_bfloat16* Vg = g_vt + (long)b*DD*NKV;

    // Q tile: 128 rows x 32 16B-segs
    #pragma unroll
    for (int t = 0; t < 16; t++) {
        int idx = t*256 + tid, row = idx >> 5, seg = idx & 31;
        CP_ASYNC16(smQ + row*QROW + seg*16, Qg + (long)row*DD + seg*8);
    }
    CP_ASYNC_COMMIT();

    auto prefetchKV = [&](int kt) {
        uint32_t sb = smKV + (kt & 1) * KV_SB;
        #pragma unroll
        for (int t = 0; t < 16; t++) {
            int idx = t*256 + tid;
            if (idx < 2048) {                 // K: 64 key-rows x 32 segs
                int row = idx >> 5, seg = idx & 31;
                CP_ASYNC16(sb + row*KROW + seg*16,
                           Kg + (long)(kt*64 + row)*DD + seg*8);
            } else {                          // V^T: 256 d-rows x 8 segs
                int j = idx - 2048;
                int row = j >> 3, seg = j & 7;
                CP_ASYNC16(sb + K_SB + row*VROW + seg*16,
                           Vg + (long)row*NKV + kt*64 + seg*8);
            }
        }
        CP_ASYNC_COMMIT();
    };
    prefetchKV(0);

    float o[32][4];
    #pragma unroll
    for (int i = 0; i < 32; i++) o[i][0] = o[i][1] = o[i][2] = o[i][3] = 0.f;
    float m0 = -1e30f, m1 = -1e30f, l0 = 0.f, l1 = 0.f;

    for (int kt = 0; kt < ntiles; kt++) {
        if (kt + 1 < ntiles) {
            __syncthreads();
            prefetchKV(kt + 1);
            CP_ASYNC_WAIT1();
        } else {
            CP_ASYNC_WAIT0();
        }
        __syncthreads();
        const uint32_t sb = smKV + (kt & 1) * KV_SB;

        // ---- S = q_tile @ k_tile^T  (warp: 16 q x 64 keys) ----
        float s[8][4] = {};
        #pragma unroll
        for (int ks = 0; ks < 16; ks++) {
            uint32_t aF[4];
            ldsm4(aF, smQ + (wid*16 + (lane & 15))*QROW
                        + (ks*16 + ((lane >> 4) & 1)*8)*2);
            #pragma unroll
            for (int g2 = 0; g2 < 4; g2++) {
                uint32_t t4[4];
                ldsm4(t4, sb + (g2*16 + ((lane >> 4) & 1)*8 + (lane & 7))*KROW
                            + (ks*16 + ((lane >> 3) & 1)*8)*2);
                mma_bf16(s[2*g2+0], aF, t4);
                mma_bf16(s[2*g2+1], aF, t4 + 2);
            }
        }
        // ---- mask last tile ----
        if (kt == ntiles - 1) {
            int kbase = kt*64 + 2*(lane & 3);
            #pragma unroll
            for (int nt = 0; nt < 8; nt++) {
                int k0 = kbase + nt*8;
                if (k0     >= vl) { s[nt][0] = -1e9f; s[nt][2] = -1e9f; }
                if (k0 + 1 >= vl) { s[nt][1] = -1e9f; s[nt][3] = -1e9f; }
            }
        }
        // ---- online softmax (rows g = lane>>2 and g+8) ----
        float rm0 = -1e30f, rm1 = -1e30f;
        #pragma unroll
        for (int nt = 0; nt < 8; nt++) {
            rm0 = fmaxf(rm0, fmaxf(s[nt][0], s[nt][1]));
            rm1 = fmaxf(rm1, fmaxf(s[nt][2], s[nt][3]));
        }
        rm0 = fmaxf(rm0, __shfl_xor_sync(0xffffffffu, rm0, 1));
        rm0 = fmaxf(rm0, __shfl_xor_sync(0xffffffffu, rm0, 2));
        rm1 = fmaxf(rm1, __shfl_xor_sync(0xffffffffu, rm1, 1));
        rm1 = fmaxf(rm1, __shfl_xor_sync(0xffffffffu, rm1, 2));
        float m0n = fmaxf(m0, rm0), m1n = fmaxf(m1, rm1);
        float f0 = __expf(m0 - m0n), f1 = __expf(m1 - m1n);

        uint32_t pr[8][2];
        float ts0 = 0.f, ts1 = 0.f;
        #pragma unroll
        for (int nt = 0; nt < 8; nt++) {
            float p0 = __expf(s[nt][0] - m0n), p1 = __expf(s[nt][1] - m0n);
            float p2 = __expf(s[nt][2] - m1n), p3 = __expf(s[nt][3] - m1n);
            ts0 += p0 + p1; ts1 += p2 + p3;
            pr[nt][0] = pack_bf16(p0, p1);
            pr[nt][1] = pack_bf16(p2, p3);
        }
        ts0 += __shfl_xor_sync(0xffffffffu, ts0, 1);
        ts0 += __shfl_xor_sync(0xffffffffu, ts0, 2);
        ts1 += __shfl_xor_sync(0xffffffffu, ts1, 1);
        ts1 += __shfl_xor_sync(0xffffffffu, ts1, 2);
        l0 = l0*f0 + ts0;  l1 = l1*f1 + ts1;
        m0 = m0n;          m1 = m1n;
        #pragma unroll
        for (int dt = 0; dt < 32; dt++) {
            o[dt][0] *= f0; o[dt][1] *= f0;
            o[dt][2] *= f1; o[dt][3] *= f1;
        }
        // ---- O += P @ V  (A = P in-register, B = V^T tile) ----
        #pragma unroll
        for (int j = 0; j < 4; j++) {
            uint32_t pa[4] = { pr[2*j][0], pr[2*j][1], pr[2*j+1][0], pr[2*j+1][1] };
            #pragma unroll
            for (int dt2 = 0; dt2 < 16; dt2++) {
                uint32_t t4[4];
                ldsm4(t4, sb + K_SB
                          + (dt2*16 + ((lane >> 4) & 1)*8 + (lane & 7))*VROW
                          + (j*16 + ((lane >> 3) & 1)*8)*2);
                mma_bf16(o[2*dt2+0], pa, t4);
                mma_bf16(o[2*dt2+1], pa, t4 + 2);
            }
        }
    }

    // ---- epilogue: normalize, pooled max over q-rows, atomicMax ----
    float inv0 = 1.f / l0, inv1 = 1.f / l1;
    #pragma unroll
    for (int dt = 0; dt < 32; dt++) {
        float c0 = fmaxf(o[dt][0]*inv0, o[dt][2]*inv1);
        float c1 = fmaxf(o[dt][1]*inv0, o[dt][3]*inv1);
        #pragma unroll
        for (int off = 4; off < 32; off <<= 1) {
            c0 = fmaxf(c0, __shfl_xor_sync(0xffffffffu, c0, off));
            c1 = fmaxf(c1, __shfl_xor_sync(0xffffffffu, c1, off));
        }
        if (lane < 4) {
            int d = dt*8 + 2*lane;
            atomicMax(&g_poolu[b*DD + d],     encf(c0));
            atomicMax(&g_poolu[b*DD + d + 1], encf(c1));
        }
    }
}

// ======================= launch =============================================
extern "C" void kernel_launch(void* const* d_in, const int* in_sizes, int n_in,
                              void* d_out, int out_size)
{
    const float* traj      = (const float*)d_in[0];
    const int*   labels    = (const int*)  d_in[1];
    const float* h         = (const float*)d_in[2];
    const int*   valid_len = (const int*)  d_in[3];
    const float* emb       = (const float*)d_in[4];
    const float* w_mlp     = (const float*)d_in[5];
    const float* b_mlp     = (const float*)d_in[6];
    const float* ln_g      = (const float*)d_in[7];
    const float* ln_b      = (const float*)d_in[8];
    const float* wq        = (const float*)d_in[9];
    const float* wk        = (const float*)d_in[11];
    const float* wv        = (const float*)d_in[13];
    const float* bq        = (const float*)d_in[10];
    const float* bk        = (const float*)d_in[12];
    const float* bv        = (const float*)d_in[14];
    const float* w_out     = (const float*)d_in[15];
    const float* b_out     = (const float*)d_in[16];
    float* out = (float*)d_out;

    cudaFuncSetAttribute(mma_gemm_kernel<1,3>, cudaFuncAttributeMaxDynamicSharedMemorySize, SMEM_REQ);
    cudaFuncSetAttribute(mma_gemm_kernel<2,2>, cudaFuncAttributeMaxDynamicSharedMemorySize, SMEM_REQ);
    cudaFuncSetAttribute(flash_kernel, cudaFuncAttributeMaxDynamicSharedMemorySize, FL_SMEM);

    __nv_bfloat16 *pxh2, *pwt2, *pwvt, *pqk, *pvt;
    float *pb2;
    cudaGetSymbolAddress((void**)&pxh2,  g_xh2);
    cudaGetSymbolAddress((void**)&pwt2,  g_wt2);
    cudaGetSymbolAddress((void**)&pwvt,  g_wvt);
    cudaGetSymbolAddress((void**)&pb2,   g_b2);
    cudaGetSymbolAddress((void**)&pqk,   g_qk);
    cudaGetSymbolAddress((void**)&pvt,   g_vt);

    // 1. x = leaky(LN(traj@w_mlp)) + le -> bf16 (slot 0); warp-per-row
    build_x_kernel<<<MTOT/8, 256>>>(traj, labels, w_mlp, b_mlp, ln_g, ln_b, emb);
    // 2. h -> bf16 (slot 1) + pool init
    conv_bf16_kernel<<<(MTOT*DD/4 + 255)/256, 256>>>(h, MTOT*DD/4);
    // 3. transposed weights (+ q pre-scale 1/16) + packed biases
    convT_all_kernel<<<3*DD, DD>>>(wq, wk, wv, bq, bk);

    // 4. q/16, k = [x;h] @ [wq/16; wk] + [bq/16; bk]  (z=2; skip k-rows >= vl)
    mma_gemm_kernel<1,3><<<dim3(2, 256, 2), 256, SMEM_REQ>>>(
        pxh2, pwt2, pb2, pqk, valid_len,
        DD, DD, (long)MTOT*DD, (long)DD*DD, (long)MTOT*DD, DD);
    // 5. vT[b][d][n] = wvT @ h^T + bv[d]  (skip n-tiles >= vl)
    mma_gemm_kernel<2,2><<<dim3(4, 2, BB), 256, SMEM_REQ>>>(
        pwvt, pxh2 + (long)MTOT*DD, bv, pvt, valid_len,
        NKV, DD, 0, (long)NKV*DD, (long)DD*NKV, 0);
    // 6. flash attention: scores + softmax + PV + max-pool (fused)
    flash_kernel<<<dim3(4, BB), 256, FL_SMEM>>>(valid_len);
    // 7. output = sigmoid((pooled + le) @ w_out + b_out)
    pool_out_kernel<<<BB, 256>>>(labels, emb, w_out, b_out, out);
}